// round 8
// baseline (speedup 1.0000x reference)
#include <cuda_runtime.h>
#include <math.h>

#define MAXN 50048
#define MAXE 640000

// ---------------- scratch (device globals) ----------------
__device__ float g_h_env[MAXN * 128];
__device__ float g_sdst_env[MAXN];     // written by k_decide (masked with -1e30)
__device__ float g_ssrc_env[MAXN];
__device__ float g_pd[2 * MAXN];       // gemm epilogue partials (per warp_n half)
__device__ float g_ps[2 * MAXN];
__device__ float2 g_sd_io[MAXN];       // (sdst_in, sdst_out)
__device__ float2 g_ss_io[MAXN];       // (ssrc_in, ssrc_out)
__device__ float4 g_hio[MAXN];         // (h_in.x, h_in.y, h_out.x, h_out.y)
__device__ float4 g_iolog[MAXN];       // (in0, in1, out0, out1) residual + aggr
__device__ float2 g_den_io[MAXN];
__device__ float  g_den_env[MAXN];
__device__ __align__(16) float2 g_e_io[MAXE];
__device__ __align__(16) float g_srel[8];  // [0,1]=in(+b) [2,3]=out(+b) [4,5]=env(+b)
// compacted surviving env edges
__device__ int  g_cnt;
__device__ int2 g_ce[MAXE];
__device__ float g_cev[MAXE];

// ---------------- helpers ----------------
__device__ __forceinline__ float lrelu(float v) { return v >= 0.f ? v : 0.2f * v; }

__device__ __forceinline__ void red_add_v2(float2* p, float a, float b) {
    asm volatile("red.global.add.v2.f32 [%0], {%1, %2};"
                 :: "l"(p), "f"(a), "f"(b) : "memory");
}
__device__ __forceinline__ void red_add_v4(float* p, float a, float b, float c, float d) {
    asm volatile("red.global.add.v4.f32 [%0], {%1, %2, %3, %4};"
                 :: "l"(p), "f"(a), "f"(b), "f"(c), "f"(d) : "memory");
}
__device__ __forceinline__ unsigned int cvt_tf32(float v) {
    unsigned int r;
    asm("cvt.rna.tf32.f32 %0, %1;" : "=r"(r) : "f"(v));
    return r;
}
__device__ __forceinline__ uint4 cvt4(float4 v) {
    return make_uint4(cvt_tf32(v.x), cvt_tf32(v.y), cvt_tf32(v.z), cvt_tf32(v.w));
}
__device__ __forceinline__ void mma8(float* c, const unsigned int* a, const unsigned int* b) {
    asm volatile(
        "mma.sync.aligned.m16n8k8.row.col.f32.tf32.tf32.f32 "
        "{%0,%1,%2,%3}, {%4,%5,%6,%7}, {%8,%9}, {%0,%1,%2,%3};"
        : "+f"(c[0]), "+f"(c[1]), "+f"(c[2]), "+f"(c[3])
        : "r"(a[0]), "r"(a[1]), "r"(a[2]), "r"(a[3]), "r"(b[0]), "r"(b[1]));
}

// =================== PHASE 1: gemm + skinny + init + rel (fused) ===================
// block ranges: [0, 2*gx) gemm | [2*gx, 2*gx+skinnyB) skinny | init blocks | last = rel
__global__ __launch_bounds__(256) void k_phase1(
    const float* __restrict__ x,
    const float* __restrict__ envW, const float* __restrict__ envWb,
    const float* __restrict__ envWres, const float* __restrict__ envWresb,
    const float* __restrict__ envAw, float* __restrict__ out1,
    const float* __restrict__ inW, const float* __restrict__ inWb,
    const float* __restrict__ inAw,
    const float* __restrict__ inWres, const float* __restrict__ inWresb,
    const float* __restrict__ outW, const float* __restrict__ outWb,
    const float* __restrict__ outAw,
    const float* __restrict__ outWres, const float* __restrict__ outWresb,
    const float* __restrict__ inWr, const float* __restrict__ inWrb,
    const float* __restrict__ inAb, const float* __restrict__ inRel,
    const float* __restrict__ outWr, const float* __restrict__ outWrb,
    const float* __restrict__ outAb, const float* __restrict__ outRel,
    const float* __restrict__ envWr, const float* __restrict__ envWrb,
    const float* __restrict__ envAb, const float* __restrict__ envRel,
    int n, int gx, int skinnyB)
{
    __shared__ __align__(16) char smem_raw[36864];
    int b = blockIdx.x;
    int tid = threadIdx.x;

    if (b < 2 * gx) {
        // ---------------- tf32 GEMM: y = x @ W^T + b ----------------
        bool env = (b < gx);
        const float* W = env ? envW : envWres;
        const float* bias = env ? envWb : envWresb;
        float* out = env ? g_h_env : out1;
        int bx = env ? b : b - gx;

        uint4 (*sx4)[9] = reinterpret_cast<uint4(*)[9]>(smem_raw);
        uint4 (*sw4)[9] = reinterpret_cast<uint4(*)[9]>(smem_raw + 18432);
        unsigned int (*sx)[36] = reinterpret_cast<unsigned int(*)[36]>(smem_raw);
        unsigned int (*sw)[36] = reinterpret_cast<unsigned int(*)[36]>(smem_raw + 18432);

        int lane = tid & 31;
        int wid = tid >> 5;
        int warp_m = wid >> 1;
        int warp_n = wid & 1;
        int g = lane >> 2, tig = lane & 3;
        int row0 = bx * 128;

        float acc[2][8][4];
#pragma unroll
        for (int mt = 0; mt < 2; mt++)
#pragma unroll
            for (int nt = 0; nt < 8; nt++)
#pragma unroll
                for (int q = 0; q < 4; q++) acc[mt][nt][q] = 0.f;

        for (int kk = 0; kk < 128; kk += 32) {
            __syncthreads();
#pragma unroll
            for (int idx = tid; idx < 1024; idx += 256) {
                int r = idx >> 3, q = idx & 7;
                float4 v = make_float4(0.f, 0.f, 0.f, 0.f);
                if (row0 + r < n) v = *(const float4*)(x + (row0 + r) * 128 + kk + q * 4);
                sx4[r][q] = cvt4(v);
                float4 wv = *(const float4*)(W + r * 128 + kk + q * 4);
                sw4[r][q] = cvt4(wv);
            }
            __syncthreads();
#pragma unroll
            for (int k0 = 0; k0 < 32; k0 += 8) {
                unsigned int a[2][4], bb[8][2];
#pragma unroll
                for (int mt = 0; mt < 2; mt++) {
                    int rb = warp_m * 32 + mt * 16;
                    a[mt][0] = sx[rb + g][k0 + tig];
                    a[mt][1] = sx[rb + g + 8][k0 + tig];
                    a[mt][2] = sx[rb + g][k0 + tig + 4];
                    a[mt][3] = sx[rb + g + 8][k0 + tig + 4];
                }
#pragma unroll
                for (int nt = 0; nt < 8; nt++) {
                    int cb = warp_n * 64 + nt * 8;
                    bb[nt][0] = sw[cb + g][k0 + tig];
                    bb[nt][1] = sw[cb + g][k0 + tig + 4];
                }
#pragma unroll
                for (int mt = 0; mt < 2; mt++)
#pragma unroll
                    for (int nt = 0; nt < 8; nt++) mma8(acc[mt][nt], a[mt], bb[nt]);
            }
        }

#pragma unroll
        for (int mt = 0; mt < 2; mt++)
#pragma unroll
            for (int rr = 0; rr < 2; rr++) {
                int row = row0 + warp_m * 32 + mt * 16 + rr * 8 + g;
                float p1 = 0.f, p2 = 0.f;
                if (row < n) {
#pragma unroll
                    for (int nt = 0; nt < 8; nt++) {
                        int col = warp_n * 64 + nt * 8 + tig * 2;
                        float v0 = acc[mt][nt][rr * 2 + 0] + bias[col];
                        float v1 = acc[mt][nt][rr * 2 + 1] + bias[col + 1];
                        *(float2*)(out + row * 128 + col) = make_float2(v0, v1);
                        if (env) {
                            p1 += v0 * envAw[col] + v1 * envAw[col + 1];
                            p2 += v0 * envAw[128 + col] + v1 * envAw[128 + col + 1];
                        }
                    }
                }
                if (env) {
                    p1 += __shfl_xor_sync(0xffffffffu, p1, 1);
                    p1 += __shfl_xor_sync(0xffffffffu, p1, 2);
                    p2 += __shfl_xor_sync(0xffffffffu, p2, 1);
                    p2 += __shfl_xor_sync(0xffffffffu, p2, 2);
                    if (tig == 0 && row < n) {
                        g_pd[warp_n * MAXN + row] = p1;
                        g_ps[warp_n * MAXN + row] = p2;
                    }
                }
            }
    } else if (b < 2 * gx + skinnyB) {
        // ---------------- skinny in/out nets ----------------
        float (*sW)[128] = reinterpret_cast<float(*)[128]>(smem_raw);
        for (int idx = tid; idx < 1024; idx += 256) {
            int j = idx >> 7, k = idx & 127;
            const float* p;
            switch (j) {
                case 0: p = inW; break;
                case 1: p = inW + 128; break;
                case 2: p = inWres; break;
                case 3: p = inWres + 128; break;
                case 4: p = outW; break;
                case 5: p = outW + 128; break;
                case 6: p = outWres; break;
                default: p = outWres + 128; break;
            }
            sW[j][k] = p[k];
        }
        __syncthreads();
        int lane = tid & 31;
        int sb = b - 2 * gx;
        int warpg = sb * 8 + (tid >> 5);
        int warps_total = skinnyB * 8;
        for (int node = warpg; node < n; node += warps_total) {
            float4 xv = *(const float4*)(x + node * 128 + lane * 4);
            float f[8];
#pragma unroll
            for (int j = 0; j < 8; j++) {
                float4 w = *(const float4*)(&sW[j][lane * 4]);
                f[j] = xv.x * w.x + xv.y * w.y + xv.z * w.z + xv.w * w.w;
            }
#pragma unroll
            for (int off = 16; off > 0; off >>= 1)
#pragma unroll
                for (int j = 0; j < 8; j++) f[j] += __shfl_xor_sync(0xffffffffu, f[j], off);
            if (lane == 0) {
                float hinx = f[0] + inWb[0], hiny = f[1] + inWb[1];
                float houx = f[4] + outWb[0], houy = f[5] + outWb[1];
                g_hio[node] = make_float4(hinx, hiny, houx, houy);
                g_iolog[node] = make_float4(f[2] + inWresb[0], f[3] + inWresb[1],
                                            f[6] + outWresb[0], f[7] + outWresb[1]);
                g_sd_io[node] = make_float2(hinx * inAw[0] + hiny * inAw[1],
                                            houx * outAw[0] + houy * outAw[1]);
                g_ss_io[node] = make_float2(hinx * inAw[2] + hiny * inAw[3],
                                            houx * outAw[2] + houy * outAw[3]);
            }
        }
    } else {
        int ib = b - 2 * gx - skinnyB;
        int nbInit = gridDim.x - 2 * gx - skinnyB - 1;
        if (ib < nbInit) {
            // ---------------- init ----------------
            int i = ib * 256 + tid;
            if (i < n) {
                g_den_io[i] = make_float2(0.f, 0.f);
                g_den_env[i] = 0.f;
            }
            if (ib == 0 && tid == 0) g_cnt = 0;
        } else {
            // ---------------- s_rel ----------------
            float* red = reinterpret_cast<float*>(smem_raw);
            int t = tid;
            for (int tt = 0; tt < 2; tt++) {
                if (t < 128) {
                    float r = envWrb[t];
                    for (int k = 0; k < 100; k++) r += envRel[tt * 100 + k] * envWr[t * 100 + k];
                    red[t] = r * envAw[256 + t];
                }
                __syncthreads();
                for (int s2 = 64; s2 > 0; s2 >>= 1) {
                    if (t < s2) red[t] += red[t + s2];
                    __syncthreads();
                }
                if (t == 0) g_srel[4 + tt] = red[0] + envAb[0];
                __syncthreads();
            }
            if (t == 0) {
                for (int tt = 0; tt < 2; tt++) {
                    float s = 0.f;
                    for (int j = 0; j < 2; j++) {
                        float r = inWrb[j];
                        for (int k = 0; k < 100; k++) r += inRel[tt * 100 + k] * inWr[j * 100 + k];
                        s += r * inAw[4 + j];
                    }
                    g_srel[tt] = s + inAb[0];
                }
            } else if (t == 32) {
                for (int tt = 0; tt < 2; tt++) {
                    float s = 0.f;
                    for (int j = 0; j < 2; j++) {
                        float r = outWrb[j];
                        for (int k = 0; k < 100; k++) r += outRel[tt * 100 + k] * outWr[j * 100 + k];
                        s += r * outAw[4 + j];
                    }
                    g_srel[2 + tt] = s + outAb[0];
                }
            }
        }
    }
}

// =================== in/out softmax pass A: 4 consecutive edges/thread ===================
__global__ void k_ioA(const int* __restrict__ ei, const int* __restrict__ et, int E) {
    int t = blockIdx.x * blockDim.x + threadIdx.x;
    int T = E >> 2;
    if (t >= T) return;
    float4 sr = *(const float4*)g_srel;   // in t0, in t1, out t0, out t1
    int4 s4 = ((const int4*)ei)[t];
    int4 d4 = ((const int4*)ei)[T + t];
    int4 y4 = ((const int4*)et)[t];
    // batched gathers
    float2 sd0 = g_sd_io[d4.x], sd1 = g_sd_io[d4.y], sd2 = g_sd_io[d4.z], sd3 = g_sd_io[d4.w];
    float2 ss0 = g_ss_io[s4.x], ss1 = g_ss_io[s4.y], ss2 = g_ss_io[s4.z], ss3 = g_ss_io[s4.w];
    float e0x = expf(lrelu(sd0.x + ss0.x + (y4.x ? sr.y : sr.x)));
    float e0y = expf(lrelu(sd0.y + ss0.y + (y4.x ? sr.w : sr.z)));
    float e1x = expf(lrelu(sd1.x + ss1.x + (y4.y ? sr.y : sr.x)));
    float e1y = expf(lrelu(sd1.y + ss1.y + (y4.y ? sr.w : sr.z)));
    float e2x = expf(lrelu(sd2.x + ss2.x + (y4.z ? sr.y : sr.x)));
    float e2y = expf(lrelu(sd2.y + ss2.y + (y4.z ? sr.w : sr.z)));
    float e3x = expf(lrelu(sd3.x + ss3.x + (y4.w ? sr.y : sr.x)));
    float e3y = expf(lrelu(sd3.y + ss3.y + (y4.w ? sr.w : sr.z)));
    float4* ep = (float4*)&g_e_io[4 * t];
    ep[0] = make_float4(e0x, e0y, e1x, e1y);
    ep[1] = make_float4(e2x, e2y, e3x, e3y);
    red_add_v2(&g_den_io[d4.x], e0x, e0y);
    red_add_v2(&g_den_io[d4.y], e1x, e1y);
    red_add_v2(&g_den_io[d4.z], e2x, e2y);
    red_add_v2(&g_den_io[d4.w], e3x, e3y);
}

// =================== in/out softmax pass B: alpha * h aggregation ===================
__global__ void k_io3(const int* __restrict__ ei, int E) {
    int t = blockIdx.x * blockDim.x + threadIdx.x;
    int T = E >> 2;
    if (t >= T) return;
    int4 s4 = ((const int4*)ei)[t];
    int4 d4 = ((const int4*)ei)[T + t];
    float4 eA = ((const float4*)g_e_io)[2 * t];
    float4 eB = ((const float4*)g_e_io)[2 * t + 1];
    float2 dn0 = g_den_io[d4.x], dn1 = g_den_io[d4.y], dn2 = g_den_io[d4.z], dn3 = g_den_io[d4.w];
    float4 h0 = g_hio[s4.x], h1 = g_hio[s4.y], h2 = g_hio[s4.z], h3 = g_hio[s4.w];
    float ai0 = eA.x / fmaxf(dn0.x, 1e-16f), ao0 = eA.y / fmaxf(dn0.y, 1e-16f);
    float ai1 = eA.z / fmaxf(dn1.x, 1e-16f), ao1 = eA.w / fmaxf(dn1.y, 1e-16f);
    float ai2 = eB.x / fmaxf(dn2.x, 1e-16f), ao2 = eB.y / fmaxf(dn2.y, 1e-16f);
    float ai3 = eB.z / fmaxf(dn3.x, 1e-16f), ao3 = eB.w / fmaxf(dn3.y, 1e-16f);
    red_add_v4((float*)&g_iolog[d4.x], ai0 * h0.x, ai0 * h0.y, ao0 * h0.z, ao0 * h0.w);
    red_add_v4((float*)&g_iolog[d4.y], ai1 * h1.x, ai1 * h1.y, ao1 * h1.z, ao1 * h1.w);
    red_add_v4((float*)&g_iolog[d4.z], ai2 * h2.x, ai2 * h2.y, ao2 * h2.z, ao2 * h2.w);
    red_add_v4((float*)&g_iolog[d4.w], ai3 * h3.x, ai3 * h3.y, ao3 * h3.z, ao3 * h3.w);
}

// =================== decide: argmax + env scalar finalize + mask ===================
__global__ void k_decide(const float* __restrict__ gi, const float* __restrict__ go, int n) {
    int i = blockIdx.x * blockDim.x + threadIdx.x;
    if (i >= n) return;
    float4 il = g_iolog[i];
    float2 a = ((const float2*)gi)[i];
    float2 b = ((const float2*)go)[i];
    bool kin = (il.x + a.x) >= (il.y + a.y);
    bool kout = (il.z + b.x) >= (il.w + b.y);
    g_sdst_env[i] = kin ? (g_pd[i] + g_pd[MAXN + i]) : -1e30f;
    g_ssrc_env[i] = kout ? (g_ps[i] + g_ps[MAXN + i]) : -1e30f;
}

// =================== env pass 1: masked logits, exp, denom, compaction ===================
__global__ __launch_bounds__(256) void k_env1(const int* __restrict__ ei,
                                              const int* __restrict__ et, int E) {
    __shared__ int sCnt, sBase;
    if (threadIdx.x == 0) sCnt = 0;
    __syncthreads();
    int t = blockIdx.x * blockDim.x + threadIdx.x;
    int T = E >> 2;
    float sr4 = g_srel[4], sr5 = g_srel[5];
    int cnt = 0;
    int2 se[4];
    float evv[4];
    if (t < T) {
        int4 s4 = ((const int4*)ei)[t];
        int4 d4 = ((const int4*)ei)[T + t];
        int4 y4 = ((const int4*)et)[t];
        float a0 = g_sdst_env[d4.x], a1 = g_sdst_env[d4.y];
        float a2 = g_sdst_env[d4.z], a3 = g_sdst_env[d4.w];
        float b0 = g_ssrc_env[s4.x], b1 = g_ssrc_env[s4.y];
        float b2 = g_ssrc_env[s4.z], b3 = g_ssrc_env[s4.w];
        float l0 = a0 + b0, l1 = a1 + b1, l2 = a2 + b2, l3 = a3 + b3;
        if (l0 > -1e20f) {
            float ev = __expf(lrelu(l0 + (y4.x ? sr5 : sr4)));
            atomicAdd(&g_den_env[d4.x], ev);
            se[cnt] = make_int2(s4.x, d4.x); evv[cnt] = ev; cnt++;
        }
        if (l1 > -1e20f) {
            float ev = __expf(lrelu(l1 + (y4.y ? sr5 : sr4)));
            atomicAdd(&g_den_env[d4.y], ev);
            se[cnt] = make_int2(s4.y, d4.y); evv[cnt] = ev; cnt++;
        }
        if (l2 > -1e20f) {
            float ev = __expf(lrelu(l2 + (y4.z ? sr5 : sr4)));
            atomicAdd(&g_den_env[d4.z], ev);
            se[cnt] = make_int2(s4.z, d4.z); evv[cnt] = ev; cnt++;
        }
        if (l3 > -1e20f) {
            float ev = __expf(lrelu(l3 + (y4.w ? sr5 : sr4)));
            atomicAdd(&g_den_env[d4.w], ev);
            se[cnt] = make_int2(s4.w, d4.w); evv[cnt] = ev; cnt++;
        }
    }
    int off = atomicAdd(&sCnt, cnt);
    __syncthreads();
    if (threadIdx.x == 0) sBase = atomicAdd(&g_cnt, sCnt);
    __syncthreads();
    int base = sBase + off;
    for (int i = 0; i < cnt; i++) {
        g_ce[base + i] = se[i];
        g_cev[base + i] = evv[i];
    }
}

// =================== env pass 2: persistent warps over compacted edges ===================
__global__ void k_env3(float* __restrict__ out) {
    int nW = (gridDim.x * blockDim.x) >> 5;
    int w = (blockIdx.x * blockDim.x + threadIdx.x) >> 5;
    int lane = threadIdx.x & 31;
    int cnt = g_cnt;
    for (; w < cnt; w += nW) {
        int2 sd = g_ce[w];
        float alpha = __fdividef(g_cev[w], g_den_env[sd.y]);
        float4 hv = ((const float4*)g_h_env)[sd.x * 32 + lane];
        red_add_v4(out + sd.y * 128 + lane * 4,
                   alpha * hv.x, alpha * hv.y, alpha * hv.z, alpha * hv.w);
    }
}

// ---------------- launch ----------------
extern "C" void kernel_launch(void* const* d_in, const int* in_sizes, int n_in,
                              void* d_out, int out_size) {
    const float* x = (const float*)d_in[0];
    const int* ei = (const int*)d_in[1];
    const int* et = (const int*)d_in[2];
    const float* gi = (const float*)d_in[3];
    const float* go = (const float*)d_in[4];
    const float* inW = (const float*)d_in[5];
    const float* inWb = (const float*)d_in[6];
    const float* inWr = (const float*)d_in[7];
    const float* inWrb = (const float*)d_in[8];
    const float* inAw = (const float*)d_in[9];
    const float* inAb = (const float*)d_in[10];
    const float* inWres = (const float*)d_in[11];
    const float* inWresb = (const float*)d_in[12];
    const float* inRel = (const float*)d_in[13];
    const float* outW = (const float*)d_in[14];
    const float* outWb = (const float*)d_in[15];
    const float* outWr = (const float*)d_in[16];
    const float* outWrb = (const float*)d_in[17];
    const float* outAw = (const float*)d_in[18];
    const float* outAb = (const float*)d_in[19];
    const float* outWres = (const float*)d_in[20];
    const float* outWresb = (const float*)d_in[21];
    const float* outRel = (const float*)d_in[22];
    const float* envW = (const float*)d_in[23];
    const float* envWb = (const float*)d_in[24];
    const float* envWr = (const float*)d_in[25];
    const float* envWrb = (const float*)d_in[26];
    const float* envAw = (const float*)d_in[27];
    const float* envAb = (const float*)d_in[28];
    const float* envWres = (const float*)d_in[29];
    const float* envWresb = (const float*)d_in[30];
    const float* envRel = (const float*)d_in[31];

    float* out = (float*)d_out;
    int n = in_sizes[0] / 128;
    int E = in_sizes[2];
    int nb = (n + 255) / 256;
    int gx = (n + 127) / 128;
    int skinnyB = 1184;
    int T = E >> 2;
    int eb = (T + 255) / 256;

    int p1blocks = 2 * gx + skinnyB + nb + 1;
    k_phase1<<<p1blocks, 256>>>(x, envW, envWb, envWres, envWresb, envAw, out,
                                inW, inWb, inAw, inWres, inWresb,
                                outW, outWb, outAw, outWres, outWresb,
                                inWr, inWrb, inAb, inRel,
                                outWr, outWrb, outAb, outRel,
                                envWr, envWrb, envAb, envRel,
                                n, gx, skinnyB);
    k_ioA<<<eb, 256>>>(ei, et, E);
    k_io3<<<eb, 256>>>(ei, E);
    k_decide<<<nb, 256>>>(gi, go, n);
    k_env1<<<eb, 256>>>(ei, et, E);
    k_env3<<<1184, 256>>>(out);
}